// round 8
// baseline (speedup 1.0000x reference)
#include <cuda_runtime.h>
#include <cuda_bf16.h>
#include <math.h>
#include <stdint.h>

// ---------------------------------------------------------------------------
// MambaFormerBlock: B=2, L=1024, D=1024, DIN=2048, DTR=64, DS=16, H=16, HD=64
// R = B*L = 2048 rows. TF32 mma.sync GEMMs with fragment-major shared layout:
// consumer loads each mma fragment with one LDS.128 / LDS.64.
// ---------------------------------------------------------------------------

#define R_ROWS   2048
#define D_MODEL  1024
#define DIN      2048
#define DTR      64
#define DS       16
#define LSEQ     1024
#define BATCH    2
#define XP_SPLIT 8

// Scratch (device globals; no allocation allowed)
__device__ float g_xnm  [R_ROWS * D_MODEL];
__device__ float g_xna  [R_ROWS * D_MODEL];
__device__ float g_xr   [R_ROWS * 2 * DIN];
__device__ float g_u    [R_ROWS * DIN];
__device__ float g_dbc  [R_ROWS * 96];
__device__ float g_xpart[XP_SPLIT * R_ROWS * 96];
__device__ float g_delta[R_ROWS * DIN];
__device__ float g_y    [R_ROWS * DIN];
__device__ float g_qkv  [R_ROWS * 1152];
__device__ float g_ao   [R_ROWS * D_MODEL];
__device__ float g_comb [R_ROWS * 2 * D_MODEL];
__device__ float g_fpre [R_ROWS * D_MODEL];

// tf32-rounded weight arena
#define W_INPROJ   0
#define W_XPROJ    (W_INPROJ + 4096*1024)
#define W_DTPROJ   (W_XPROJ + 96*2048)
#define W_OUTPROJ  (W_DTPROJ + 2048*64)
#define W_QKV      (W_OUTPROJ + 1024*2048)
#define W_OATTN    (W_QKV + 1152*1024)
#define W_FUSE     (W_OATTN + 1024*1024)
#define W_TOTAL    (W_FUSE + 1024*2048)
__device__ float g_wtf[W_TOTAL];

__device__ __forceinline__ unsigned f2tf(float x) {
    unsigned u;
    asm("cvt.rna.tf32.f32 %0, %1;" : "=r"(u) : "f"(x));
    return u;
}
__device__ __forceinline__ float f2tf_f(float x) { return __uint_as_float(f2tf(x)); }

// round-to-tf32 copy (float4 granularity; n must be multiple of 4)
__global__ void __launch_bounds__(256) round_tf32_kernel(
    const float* __restrict__ src, float* __restrict__ dst, int n4)
{
    int i = blockIdx.x * 256 + threadIdx.x;
    if (i < n4) {
        float4 v = ((const float4*)src)[i];
        v.x = f2tf_f(v.x); v.y = f2tf_f(v.y); v.z = f2tf_f(v.z); v.w = f2tf_f(v.w);
        ((float4*)dst)[i] = v;
    }
}

// ---------------------------------------------------------------------------
// LayerNorm (optionally two (w,b) pairs sharing the same stats). rnd -> tf32.
// ---------------------------------------------------------------------------
__global__ void __launch_bounds__(256) ln_dual_kernel(
    const float* __restrict__ x,
    const float* __restrict__ w1, const float* __restrict__ b1, float* __restrict__ o1,
    const float* __restrict__ w2, const float* __restrict__ b2, float* __restrict__ o2,
    int rnd)
{
    const int Dm = D_MODEL;
    int row = blockIdx.x;
    const float* xp = x + (size_t)row * Dm;
    float s = 0.f, s2 = 0.f;
    for (int i = threadIdx.x; i < Dm; i += 256) { float v = xp[i]; s += v; s2 += v * v; }
    #pragma unroll
    for (int off = 16; off; off >>= 1) {
        s  += __shfl_xor_sync(0xffffffffu, s,  off);
        s2 += __shfl_xor_sync(0xffffffffu, s2, off);
    }
    __shared__ float rs[8], rs2[8];
    __shared__ float mean_s, inv_s;
    int w = threadIdx.x >> 5, l = threadIdx.x & 31;
    if (!l) { rs[w] = s; rs2[w] = s2; }
    __syncthreads();
    if (threadIdx.x == 0) {
        float a = 0.f, a2 = 0.f;
        #pragma unroll
        for (int i = 0; i < 8; i++) { a += rs[i]; a2 += rs2[i]; }
        float mean = a / Dm;
        float var  = a2 / Dm - mean * mean;
        mean_s = mean;
        inv_s  = rsqrtf(var + 1e-5f);
    }
    __syncthreads();
    float mean = mean_s, inv = inv_s;
    for (int i = threadIdx.x; i < Dm; i += 256) {
        float v = (xp[i] - mean) * inv;
        float a = v * w1[i] + b1[i];
        o1[(size_t)row * Dm + i] = rnd ? f2tf_f(a) : a;
        if (o2) {
            float c = v * w2[i] + b2[i];
            o2[(size_t)row * Dm + i] = rnd ? f2tf_f(c) : c;
        }
    }
}

// ---------------------------------------------------------------------------
// TF32 tensor-core GEMM, fragment-major smem. C = A[M,K] @ W[N,K]^T
// BM=128, BN=128, BK=16, 256 threads (8 warps, warp tile 64x32 of m16n8k8).
// Fragment layout:
//   A: chunk (s*8+m), 32 lanes x float4 (a0..a3)  -> LDS.128 per frag
//   B: chunk (s*16+nb), 32 lanes x float2 (b0,b1) -> LDS.64 per frag
// ---------------------------------------------------------------------------
__device__ __forceinline__ void mma_tf32(float* d, const unsigned* a, const unsigned* b) {
    asm volatile(
        "mma.sync.aligned.m16n8k8.row.col.f32.tf32.tf32.f32 "
        "{%0,%1,%2,%3}, {%4,%5,%6,%7}, {%8,%9}, {%0,%1,%2,%3};"
        : "+f"(d[0]), "+f"(d[1]), "+f"(d[2]), "+f"(d[3])
        : "r"(a[0]), "r"(a[1]), "r"(a[2]), "r"(a[3]), "r"(b[0]), "r"(b[1]));
}

__global__ void __launch_bounds__(256, 2) gemm_tf32_kernel(
    const float* __restrict__ A, int lda,
    const float* __restrict__ W, int ldw,
    int klen,
    const float* __restrict__ bias,
    const float* __restrict__ resid, int ldr,
    float* __restrict__ C, int ldc,
    int N, int act, int rnd)
{
    __shared__ float fa[2][2048];
    __shared__ float fb[2][2048];

    const int tid  = threadIdx.x;
    const int lane = tid & 31;
    const int wid  = tid >> 5;
    const int m0w  = (wid & 1) * 4;    // m16-block base (0 or 4)
    const int n0w  = (wid >> 1) * 4;   // n8-block base (0,4,8,12)
    const int qr   = lane >> 2;
    const int qc   = lane & 3;

    const int bm = blockIdx.y * 128;
    const int bn = blockIdx.x * 128;
    const int ks = blockIdx.z * klen;

    // producer: two float4 per matrix per tile
    const int fid0 = tid, fid1 = tid + 256;
    const int rA0 = fid0 >> 2, cA0 = fid0 & 3;
    const int rA1 = fid1 >> 2, cA1 = fid1 & 3;
    const float* pA0 = A + (size_t)(bm + rA0) * lda + ks + cA0 * 4;
    const float* pA1 = A + (size_t)(bm + rA1) * lda + ks + cA1 * 4;
    const bool wok0 = (bn + rA0) < N;
    const bool wok1 = (bn + rA1) < N;
    const float* pW0 = W + (size_t)(wok0 ? bn + rA0 : 0) * ldw + ks + cA0 * 4;
    const float* pW1 = W + (size_t)(wok1 ? bn + rA1 : 0) * ldw + ks + cA1 * 4;

    // STS base offsets (element j adds j*4 for A, j*2 for B)
    #define ABASE(r, ch) ((((((ch) >> 1) * 8 + ((r) >> 4)) * 32 + ((r) & 7) * 4) * 4) \
                          + (((r) >> 3) & 1) + 2 * ((ch) & 1))
    #define BBASE(n, ch) ((((((ch) >> 1) * 16 + ((n) >> 3)) * 32 + ((n) & 7) * 4) * 2) \
                          + ((ch) & 1))
    const int aB0 = ABASE(rA0, cA0), aB1 = ABASE(rA1, cA1);
    const int bB0 = BBASE(rA0, cA0), bB1 = BBASE(rA1, cA1);
    #undef ABASE
    #undef BBASE

    #define STS_A(buf, base, v) { fa[buf][(base)] = (v).x; fa[buf][(base)+4] = (v).y; \
                                  fa[buf][(base)+8] = (v).z; fa[buf][(base)+12] = (v).w; }
    #define STS_B(buf, base, v) { fb[buf][(base)] = (v).x; fb[buf][(base)+2] = (v).y; \
                                  fb[buf][(base)+4] = (v).z; fb[buf][(base)+6] = (v).w; }

    float acc[4][4][4];
    #pragma unroll
    for (int i = 0; i < 4; i++)
        #pragma unroll
        for (int j = 0; j < 4; j++)
            #pragma unroll
            for (int r = 0; r < 4; r++) acc[i][j][r] = 0.f;

    const int nk = klen >> 4;
    const float4 zero4 = make_float4(0.f, 0.f, 0.f, 0.f);
    float4 va0, va1, vw0, vw1;

    // prologue: tile 0 -> stage 0
    va0 = *(const float4*)pA0;
    va1 = *(const float4*)pA1;
    vw0 = wok0 ? *(const float4*)pW0 : zero4;
    vw1 = wok1 ? *(const float4*)pW1 : zero4;
    STS_A(0, aB0, va0); STS_A(0, aB1, va1);
    STS_B(0, bB0, vw0); STS_B(0, bB1, vw1);
    __syncthreads();

    for (int kt = 0; kt < nk; kt++) {
        const int cur = kt & 1;
        const bool hn = (kt + 1) < nk;
        if (hn) {
            const int off = (kt + 1) * 16;
            va0 = *(const float4*)(pA0 + off);
            va1 = *(const float4*)(pA1 + off);
            vw0 = wok0 ? *(const float4*)(pW0 + off) : zero4;
            vw1 = wok1 ? *(const float4*)(pW1 + off) : zero4;
        }
        #pragma unroll
        for (int s = 0; s < 2; s++) {
            unsigned af[4][4], bf[4][2];
            #pragma unroll
            for (int mt = 0; mt < 4; mt++) {
                float4 v = *(const float4*)&fa[cur][((s * 8 + m0w + mt) * 32 + lane) * 4];
                af[mt][0] = __float_as_uint(v.x); af[mt][1] = __float_as_uint(v.y);
                af[mt][2] = __float_as_uint(v.z); af[mt][3] = __float_as_uint(v.w);
            }
            #pragma unroll
            for (int nt = 0; nt < 4; nt++) {
                float2 v = *(const float2*)&fb[cur][((s * 16 + n0w + nt) * 32 + lane) * 2];
                bf[nt][0] = __float_as_uint(v.x); bf[nt][1] = __float_as_uint(v.y);
            }
            #pragma unroll
            for (int mt = 0; mt < 4; mt++)
                #pragma unroll
                for (int nt = 0; nt < 4; nt++)
                    mma_tf32(acc[mt][nt], af[mt], bf[nt]);
        }
        if (hn) {
            const int nx = 1 - cur;
            STS_A(nx, aB0, va0); STS_A(nx, aB1, va1);
            STS_B(nx, bB0, vw0); STS_B(nx, bB1, vw1);
            __syncthreads();
        }
    }
    #undef STS_A
    #undef STS_B

    // epilogue
    #pragma unroll
    for (int mt = 0; mt < 4; mt++) {
        #pragma unroll
        for (int nt = 0; nt < 4; nt++) {
            int r = bm + (m0w + mt) * 16 + qr;
            int c = bn + (n0w + nt) * 8 + 2 * qc;
            #pragma unroll
            for (int half = 0; half < 2; half++) {
                int rr = r + half * 8;
                #pragma unroll
                for (int cc = 0; cc < 2; cc++) {
                    int gc = c + cc;
                    if (gc < N) {
                        float v = acc[mt][nt][half * 2 + cc];
                        if (bias)  v += bias[gc];
                        if (act)   v = (v > 20.f) ? v : log1pf(__expf(v));
                        if (resid) v += resid[(size_t)rr * ldr + gc];
                        if (rnd)   v = f2tf_f(v);
                        C[(size_t)rr * ldc + gc] = v;
                    }
                }
            }
        }
    }
}

// reduce split-K partials for x_proj (round to tf32: feeds dt_proj GEMM)
__global__ void __launch_bounds__(256) reduce_xp_kernel(
    const float* __restrict__ part, float* __restrict__ out)
{
    int i = blockIdx.x * 256 + threadIdx.x;
    const int total = R_ROWS * 96;
    if (i < total) {
        float s = 0.f;
        #pragma unroll
        for (int z = 0; z < XP_SPLIT; z++) s += part[(size_t)z * total + i];
        out[i] = f2tf_f(s);
    }
}

// ---------------------------------------------------------------------------
// Depthwise causal conv (width 4) along L + bias + SiLU. Output tf32-rounded.
// ---------------------------------------------------------------------------
__global__ void __launch_bounds__(256) conv_silu_kernel(
    const float* __restrict__ xr,
    const float* __restrict__ cw, const float* __restrict__ cb,
    float* __restrict__ u)
{
    int idx = blockIdx.x * 256 + threadIdx.x;
    int d = idx & (DIN - 1);
    int r = idx >> 11;
    int l = r & (LSEQ - 1);
    float acc = cb[d];
    const float* base = xr + (size_t)r * (2 * DIN) + d;
    #pragma unroll
    for (int k = 0; k < 4; k++) {
        int l2 = l - 3 + k;
        if (l2 >= 0) acc += cw[d * 4 + k] * base[(size_t)(l2 - l) * (2 * DIN)];
    }
    float sv = acc / (1.f + __expf(-acc));
    u[idx] = f2tf_f(sv);
}

// ---------------------------------------------------------------------------
// Selective scan. 16 lanes per (b,d) chain. Output tf32-rounded (feeds GEMM).
// ---------------------------------------------------------------------------
__global__ void __launch_bounds__(256) scan_kernel(
    const float* __restrict__ delta, const float* __restrict__ u,
    const float* __restrict__ dbc,   const float* __restrict__ xr,
    const float* __restrict__ A_log, const float* __restrict__ Dskip,
    float* __restrict__ y)
{
    int t = blockIdx.x * 256 + threadIdx.x;
    int chain = t >> 4;
    int n = t & 15;
    int b = chain >> 11;
    int d = chain & (DIN - 1);
    float An = -__expf(A_log[d * DS + n]);
    float Dv = Dskip[d];
    float h = 0.f;
    size_t rowbase = (size_t)b * LSEQ;
    for (int l = 0; l < LSEQ; l++) {
        size_t row = rowbase + l;
        float dv = delta[row * DIN + d];
        float uv = u[row * DIN + d];
        float Bn = dbc[row * 96 + DTR + n];
        float Cn = dbc[row * 96 + DTR + DS + n];
        h = __expf(dv * An) * h + dv * Bn * uv;
        float p = h * Cn;
        p += __shfl_xor_sync(0xffffffffu, p, 8, 16);
        p += __shfl_xor_sync(0xffffffffu, p, 4, 16);
        p += __shfl_xor_sync(0xffffffffu, p, 2, 16);
        p += __shfl_xor_sync(0xffffffffu, p, 1, 16);
        if (n == 0) {
            float res = xr[row * (2 * DIN) + DIN + d];
            float sres = res / (1.f + __expf(-res));
            y[row * DIN + d] = f2tf_f((p + uv * Dv) * sres);
        }
    }
}

// ---------------------------------------------------------------------------
// Causal MQA attention. Output tf32-rounded (feeds oattn GEMM).
// ---------------------------------------------------------------------------
__global__ void __launch_bounds__(128) attn_kernel(
    const float* __restrict__ qkv, float* __restrict__ out)
{
    __shared__ float ks[64 * 64];
    __shared__ float vs[64 * 64];
    int b = blockIdx.z, h = blockIdx.y;
    int ql = blockIdx.x * 128 + threadIdx.x;
    size_t qrow = ((size_t)b * LSEQ + ql) * 1152;
    float4 q4[16];
    #pragma unroll
    for (int i = 0; i < 16; i++) q4[i] = *(const float4*)(qkv + qrow + h * 64 + i * 4);
    float4 o4[16];
    #pragma unroll
    for (int i = 0; i < 16; i++) o4[i] = make_float4(0.f, 0.f, 0.f, 0.f);
    float m = -1e30f, lsum = 0.f;
    int ntiles = blockIdx.x * 2 + 2;
    for (int tk = 0; tk < ntiles; tk++) {
        int s0 = tk * 64;
        __syncthreads();
        for (int i = threadIdx.x; i < 64 * 16; i += 128) {
            int s = i >> 4, jj = i & 15;
            const float* kr = qkv + ((size_t)b * LSEQ + s0 + s) * 1152;
            ((float4*)ks)[i] = *(const float4*)(kr + 1024 + jj * 4);
            ((float4*)vs)[i] = *(const float4*)(kr + 1088 + jj * 4);
        }
        __syncthreads();
        int kcount = ql - s0 + 1;
        if (kcount > 64) kcount = 64;
        for (int s = 0; s < kcount; s++) {
            const float4* kp = (const float4*)(ks + s * 64);
            float sc = 0.f;
            #pragma unroll
            for (int i = 0; i < 16; i++) {
                float4 kk = kp[i];
                sc += q4[i].x * kk.x; sc += q4[i].y * kk.y;
                sc += q4[i].z * kk.z; sc += q4[i].w * kk.w;
            }
            sc *= 0.125f;
            const float4* vp = (const float4*)(vs + s * 64);
            if (sc <= m) {
                float p = __expf(sc - m);
                lsum += p;
                #pragma unroll
                for (int i = 0; i < 16; i++) {
                    float4 vv = vp[i];
                    o4[i].x += p * vv.x; o4[i].y += p * vv.y;
                    o4[i].z += p * vv.z; o4[i].w += p * vv.w;
                }
            } else {
                float sc2 = __expf(m - sc);
                m = sc;
                lsum = lsum * sc2 + 1.f;
                #pragma unroll
                for (int i = 0; i < 16; i++) {
                    float4 vv = vp[i];
                    o4[i].x = o4[i].x * sc2 + vv.x; o4[i].y = o4[i].y * sc2 + vv.y;
                    o4[i].z = o4[i].z * sc2 + vv.z; o4[i].w = o4[i].w * sc2 + vv.w;
                }
            }
        }
    }
    float inv = 1.f / lsum;
    float* op = out + ((size_t)b * LSEQ + ql) * D_MODEL + h * 64;
    #pragma unroll
    for (int i = 0; i < 16; i++) {
        float4 vv;
        vv.x = f2tf_f(o4[i].x * inv); vv.y = f2tf_f(o4[i].y * inv);
        vv.z = f2tf_f(o4[i].z * inv); vv.w = f2tf_f(o4[i].w * inv);
        *(float4*)(op + i * 4) = vv;
    }
}

// ---------------------------------------------------------------------------
// Launch
// ---------------------------------------------------------------------------
extern "C" void kernel_launch(void* const* d_in, const int* in_sizes, int n_in,
                              void* d_out, int out_size)
{
    const float* x          = (const float*)d_in[0];
    const float* mnorm_w    = (const float*)d_in[1];
    const float* mnorm_b    = (const float*)d_in[2];
    const float* in_proj_w  = (const float*)d_in[3];
    const float* conv_w     = (const float*)d_in[4];
    const float* conv_b     = (const float*)d_in[5];
    const float* x_proj_w   = (const float*)d_in[6];
    const float* dt_proj_w  = (const float*)d_in[7];
    const float* dt_proj_b  = (const float*)d_in[8];
    const float* A_log      = (const float*)d_in[9];
    const float* D_skip     = (const float*)d_in[10];
    const float* out_proj_w = (const float*)d_in[11];
    const float* norm1_w    = (const float*)d_in[12];
    const float* norm1_b    = (const float*)d_in[13];
    const float* wqkv_w     = (const float*)d_in[14];
    const float* wqkv_b     = (const float*)d_in[15];
    const float* oattn_w    = (const float*)d_in[16];
    const float* oattn_b    = (const float*)d_in[17];
    const float* fuse_w     = (const float*)d_in[18];
    const float* fuse_b     = (const float*)d_in[19];
    const float* fln_w      = (const float*)d_in[20];
    const float* fln_b      = (const float*)d_in[21];
    float* out = (float*)d_out;

    float *xnm, *xna, *xr, *u, *dbc, *xpart, *delta, *y, *qkv, *ao, *comb, *fpre, *wtf;
    cudaGetSymbolAddress((void**)&xnm,   g_xnm);
    cudaGetSymbolAddress((void**)&xna,   g_xna);
    cudaGetSymbolAddress((void**)&xr,    g_xr);
    cudaGetSymbolAddress((void**)&u,     g_u);
    cudaGetSymbolAddress((void**)&dbc,   g_dbc);
    cudaGetSymbolAddress((void**)&xpart, g_xpart);
    cudaGetSymbolAddress((void**)&delta, g_delta);
    cudaGetSymbolAddress((void**)&y,     g_y);
    cudaGetSymbolAddress((void**)&qkv,   g_qkv);
    cudaGetSymbolAddress((void**)&ao,    g_ao);
    cudaGetSymbolAddress((void**)&comb,  g_comb);
    cudaGetSymbolAddress((void**)&fpre,  g_fpre);
    cudaGetSymbolAddress((void**)&wtf,   g_wtf);

    // 0. pre-round all GEMM weights to tf32
    #define RND(srcp, off, n) \
        round_tf32_kernel<<<((n)/4 + 255)/256, 256>>>(srcp, wtf + off, (n)/4)
    RND(in_proj_w,  W_INPROJ,  4096*1024);
    RND(x_proj_w,   W_XPROJ,   96*2048);
    RND(dt_proj_w,  W_DTPROJ,  2048*64);
    RND(out_proj_w, W_OUTPROJ, 1024*2048);
    RND(wqkv_w,     W_QKV,     1152*1024);
    RND(oattn_w,    W_OATTN,   1024*1024);
    RND(fuse_w,     W_FUSE,    1024*2048);
    #undef RND

    // 1. Both input LayerNorms (shared stats), tf32-rounded outputs
    ln_dual_kernel<<<R_ROWS, 256>>>(x, mnorm_w, mnorm_b, xnm, norm1_w, norm1_b, xna, 1);

    // 2. in_proj: xr = xnm @ in_proj_w^T   (2048 x 4096, K=1024)
    gemm_tf32_kernel<<<dim3(4096/128, R_ROWS/128, 1), 256>>>(
        xnm, D_MODEL, wtf + W_INPROJ, D_MODEL, D_MODEL,
        nullptr, nullptr, 0, xr, 2*DIN, 2*DIN, 0, 0);

    // 3. depthwise conv + SiLU -> u (tf32)
    conv_silu_kernel<<<(R_ROWS * DIN) / 256, 256>>>(xr, conv_w, conv_b, u);

    // 4. x_proj split-K: partials (2048 x 96, K=2048, 8 slices of 256)
    gemm_tf32_kernel<<<dim3(1, R_ROWS/128, XP_SPLIT), 256>>>(
        u, DIN, wtf + W_XPROJ, DIN, DIN/XP_SPLIT,
        nullptr, nullptr, 0, xpart, 96, 96, 0, 0);
    reduce_xp_kernel<<<(R_ROWS * 96 + 255) / 256, 256>>>(xpart, dbc);

    // 5. dt_proj + softplus: delta (2048 x 2048, K=64, lda=96)
    gemm_tf32_kernel<<<dim3(DIN/128, R_ROWS/128, 1), 256>>>(
        dbc, 96, wtf + W_DTPROJ, DTR, DTR,
        dt_proj_b, nullptr, 0, delta, DIN, DIN, 1, 0);

    // 6. selective scan (+ D_skip + silu(res) gate) -> y (tf32)
    scan_kernel<<<(BATCH * DIN * 16) / 256, 256>>>(delta, u, dbc, xr, A_log, D_skip, y);

    // 7. out_proj + residual x -> comb[:, :1024] (tf32: feeds fuse)
    gemm_tf32_kernel<<<dim3(D_MODEL/128, R_ROWS/128, 1), 256>>>(
        y, DIN, wtf + W_OUTPROJ, DIN, DIN,
        nullptr, x, D_MODEL, comb, 2*D_MODEL, D_MODEL, 0, 1);

    // 8. wqkv (+bias): qkv (2048 x 1152, K=1024)
    gemm_tf32_kernel<<<dim3(1152/128, R_ROWS/128, 1), 256>>>(
        xna, D_MODEL, wtf + W_QKV, D_MODEL, D_MODEL,
        wqkv_b, nullptr, 0, qkv, 1152, 1152, 0, 0);

    // 9. causal MQA attention -> ao (tf32)
    attn_kernel<<<dim3(LSEQ/128, 16, BATCH), 128>>>(qkv, ao);

    // 10. oattn (+bias) + residual x -> comb[:, 1024:] (tf32: feeds fuse)
    gemm_tf32_kernel<<<dim3(D_MODEL/128, R_ROWS/128, 1), 256>>>(
        ao, D_MODEL, wtf + W_OATTN, D_MODEL, D_MODEL,
        oattn_b, x, D_MODEL, comb + D_MODEL, 2*D_MODEL, D_MODEL, 0, 1);

    // 11. fuse GEMM (+bias): fpre = comb @ fuse_w^T  (2048 x 1024, K=2048)
    gemm_tf32_kernel<<<dim3(D_MODEL/128, R_ROWS/128, 1), 256>>>(
        comb, 2*D_MODEL, wtf + W_FUSE, 2*D_MODEL, 2*D_MODEL,
        fuse_b, nullptr, 0, fpre, D_MODEL, D_MODEL, 0, 0);

    // 12. final LayerNorm -> out (no rounding)
    ln_dual_kernel<<<R_ROWS, 256>>>(fpre, fln_w, fln_b, out, nullptr, nullptr, nullptr, 0);
}